// round 10
// baseline (speedup 1.0000x reference)
#include <cuda_runtime.h>
#include <cuda_bf16.h>
#include <cstdint>

#define B_ROOT   8192
#define KFAN     16
#define NCHILD   (B_ROOT * KFAN)     // 131072
#define VOCAB    50000
#define DIM      64
#define CR       8
#define NR       64
#define CC       16
#define NC       128
#define OUTD     32
#define KDIM     (CC * DIM + NC)     // 1152
#define OUTCOLS  (CR * DIM + NR + OUTD)  // 608
#define EPSBN    1e-5f

#define PROJ_SPAN 512
#define VTILES    ((VOCAB + PROJ_SPAN - 1) / PROJ_SPAN)   // 98
#define SC_BLKS   (NCHILD / 256)                    // 512
#define SR_BLKS   (B_ROOT / 128)                    // 64
#define BIG1_BLKS (SC_BLKS + SR_BLKS + CC * VTILES) // 2144

#define CH_BLKS   (B_ROOT / 4)                      // 2048 (4 roots per 128-thr block)
#define RT_BLKS   (B_ROOT / 4)                      // 2048
#define BIG2_BLKS (CH_BLKS + RT_BLKS)               // 4096

// big2 smem layout (floats): Wn_s[128*36] then per-warp {hs 16*132, buf 16*36, cats 256(int), gs 16(int)}
#define WNS_FLOATS   (NC * 36)                       // 4608
#define WARP_FLOATS  (16*132 + 16*36 + 256 + 16)     // 2960
#define BIG2_SMEM    ((WNS_FLOATS + 4 * WARP_FLOATS) * 4)   // 65792 B

// ---------------- scratch (device globals; allocation-free) ----------------
__device__ __align__(16) double g_sum_c[NC];
__device__ __align__(16) double g_ss_c [NC];
__device__ __align__(16) double g_sum_r[NR];
__device__ __align__(16) double g_ss_r [NR];
__device__ __align__(16) float g_a_c[NC];
__device__ __align__(16) float g_s_c[NC];
__device__ __align__(16) float g_a_r[NR];
__device__ __align__(16) float g_s_r[NR];
__device__ __align__(16) float g_wt[NC * OUTD];   // tf32-rounded W numeric slice [k][o]
// bf16-packed categorical projection: 16 bf16x2 words per (c,v) row = 64 B
__device__ __align__(256) unsigned g_projp[CC * VOCAB * (OUTD / 2)];   // 51.2 MB

// ---------------- helpers ----------------
__device__ __forceinline__ unsigned long long pack2(float a, float b) {
    unsigned long long r;
    asm("mov.b64 %0, {%1, %2};" : "=l"(r) : "f"(a), "f"(b));
    return r;
}
__device__ __forceinline__ void unpack2(unsigned long long v, float& lo, float& hi) {
    asm("mov.b64 {%0, %1}, %2;" : "=f"(lo), "=f"(hi) : "l"(v));
}
__device__ __forceinline__ void fma2(unsigned long long& d, unsigned long long a, unsigned long long b) {
    asm("fma.rn.f32x2 %0, %1, %2, %0;" : "+l"(d) : "l"(a), "l"(b));
}
__device__ __forceinline__ unsigned tf32r(float x) {
    unsigned u;
    asm("cvt.rna.tf32.f32 %0, %1;" : "=r"(u) : "f"(x));
    return u;
}
__device__ __forceinline__ void mma_tf32(float& d0, float& d1, float& d2, float& d3,
                                         unsigned a0, unsigned a1, unsigned a2, unsigned a3,
                                         unsigned b0, unsigned b1) {
    asm volatile("mma.sync.aligned.m16n8k8.row.col.f32.tf32.tf32.f32 "
        "{%0,%1,%2,%3}, {%4,%5,%6,%7}, {%8,%9}, {%0,%1,%2,%3};"
        : "+f"(d0), "+f"(d1), "+f"(d2), "+f"(d3)
        : "r"(a0), "r"(a1), "r"(a2), "r"(a3), "r"(b0), "r"(b1));
}
// accumulate a uint4 of bf16x2 (8 outputs) into 8 fp32 accs
__device__ __forceinline__ void acc8(float* s, uint4 u) {
    unsigned w[4] = {u.x, u.y, u.z, u.w};
#pragma unroll
    for (int j = 0; j < 4; ++j) {
        __nv_bfloat162 b2 = *reinterpret_cast<__nv_bfloat162*>(&w[j]);
        float2 f = __bfloat1622float2(b2);
        s[2 * j]     += f.x;
        s[2 * j + 1] += f.y;
    }
}

// ---------------- kernel 0: reset ----------------
__global__ void k_reset() {
    int t = threadIdx.x;
    if (t < NC) { g_sum_c[t] = 0.0; g_ss_c[t] = 0.0; }
    if (t < NR) { g_sum_r[t] = 0.0; g_ss_r[t] = 0.0; }
}

// ---------------- kernel 1: big1 = stats_child ∪ stats_root ∪ proj (unchanged from R9) ----
__global__ __launch_bounds__(256, 2)
void k_big1(const int* __restrict__ cfi, const float* __restrict__ child_num,
            const int* __restrict__ idx, const float* __restrict__ root_num,
            const float* __restrict__ emb_child, const float* __restrict__ W) {
    extern __shared__ float sm[];
    int bid = blockIdx.x;
    int t = threadIdx.x;

    if (bid < SC_BLKS) {
        int* rid = (int*)sm;
        rid[t] = cfi[bid * 256 + t];
        __syncthreads();
        int col = t & 127;
        int r0 = (t >> 7) * 128;
        float s[8], ss[8];
#pragma unroll
        for (int u = 0; u < 8; ++u) { s[u] = 0.f; ss[u] = 0.f; }
        for (int r = r0; r < r0 + 128; r += 8) {
            float x[8];
#pragma unroll
            for (int u = 0; u < 8; ++u) {
                int g = rid[r + u];
                x[u] = __ldg(&child_num[(size_t)g * NC + col]);
            }
#pragma unroll
            for (int u = 0; u < 8; ++u) { s[u] += x[u]; ss[u] += x[u] * x[u]; }
        }
        float st  = (s[0]+s[1])+(s[2]+s[3])+((s[4]+s[5])+(s[6]+s[7]));
        float sst = (ss[0]+ss[1])+(ss[2]+ss[3])+((ss[4]+ss[5])+(ss[6]+ss[7]));
        atomicAdd(&g_sum_c[col], (double)st);
        atomicAdd(&g_ss_c[col],  (double)sst);
        return;
    }
    if (bid < SC_BLKS + SR_BLKS) {
        int b = bid - SC_BLKS;
        int* rid = (int*)sm;
        if (t < 128) rid[t] = idx[b * 128 + t];
        __syncthreads();
        int col = t & 63;
        int r0 = (t >> 6) * 32;
        float s[4], ss[4];
#pragma unroll
        for (int u = 0; u < 4; ++u) { s[u] = 0.f; ss[u] = 0.f; }
        for (int r = r0; r < r0 + 32; r += 4) {
            float x[4];
#pragma unroll
            for (int u = 0; u < 4; ++u) {
                int g = rid[r + u];
                x[u] = __ldg(&root_num[(size_t)g * NR + col]);
            }
#pragma unroll
            for (int u = 0; u < 4; ++u) { s[u] += x[u]; ss[u] += x[u] * x[u]; }
        }
        atomicAdd(&g_sum_r[col], (double)((s[0]+s[1])+(s[2]+s[3])));
        atomicAdd(&g_ss_r[col],  (double)((ss[0]+ss[1])+(ss[2]+ss[3])));
        return;
    }

    int pb = bid - (SC_BLKS + SR_BLKS);
    int c  = pb / VTILES;
    int v0 = (pb % VTILES) * PROJ_SPAN;

    float* Ws = sm;                          // [DIM][OUTD]
    for (int i = t; i < DIM * OUTD; i += 256) {
        int o = i >> 6, d = i & 63;
        Ws[d * OUTD + o] = W[(size_t)o * KDIM + c * DIM + d];
    }
    __syncthreads();

    int va = v0 + t;
    int vb = va + 256;
    bool ga = va < VOCAB, gb = vb < VOCAB;
    const float4* ea4 = (const float4*)(emb_child + ((size_t)c * VOCAB + va) * DIM);
    const float4* eb4 = (const float4*)(emb_child + ((size_t)c * VOCAB + vb) * DIM);
    const float4 z4 = make_float4(0.f, 0.f, 0.f, 0.f);

    unsigned long long acc0[16], acc1[16];
#pragma unroll
    for (int j = 0; j < 16; ++j) { acc0[j] = pack2(0.f, 0.f); acc1[j] = pack2(0.f, 0.f); }

    float4 e0 = ga ? ea4[0] : z4;
    float4 e1 = gb ? eb4[0] : z4;
#pragma unroll 1
    for (int jb = 0; jb < 16; ++jb) {
        float4 n0 = z4, n1 = z4;
        if (jb < 15) {
            if (ga) n0 = ea4[jb + 1];
            if (gb) n1 = eb4[jb + 1];
        }
        const float ev0[4] = {e0.x, e0.y, e0.z, e0.w};
        const float ev1[4] = {e1.x, e1.y, e1.z, e1.w};
#pragma unroll
        for (int q = 0; q < 4; ++q) {
            int d = 4 * jb + q;
            unsigned long long h0 = pack2(ev0[q], ev0[q]);
            unsigned long long h1 = pack2(ev1[q], ev1[q]);
            const ulonglong2* wr = (const ulonglong2*)(Ws + d * OUTD);
#pragma unroll
            for (int p = 0; p < 8; ++p) {
                ulonglong2 w = wr[p];
                fma2(acc0[2 * p],     h0, w.x);
                fma2(acc0[2 * p + 1], h0, w.y);
                fma2(acc1[2 * p],     h1, w.x);
                fma2(acc1[2 * p + 1], h1, w.y);
            }
        }
        e0 = n0; e1 = n1;
    }

    if (ga) {
        unsigned us[16];
#pragma unroll
        for (int j = 0; j < 16; ++j) {
            float lo, hi; unpack2(acc0[j], lo, hi);
            __nv_bfloat162 b2 = __float22bfloat162_rn(make_float2(lo, hi));
            us[j] = *reinterpret_cast<unsigned*>(&b2);
        }
        uint4* outp = (uint4*)(g_projp + ((size_t)c * VOCAB + va) * 16);
        outp[0] = make_uint4(us[0],  us[1],  us[2],  us[3]);
        outp[1] = make_uint4(us[4],  us[5],  us[6],  us[7]);
        outp[2] = make_uint4(us[8],  us[9],  us[10], us[11]);
        outp[3] = make_uint4(us[12], us[13], us[14], us[15]);
    }
    if (gb) {
        unsigned us[16];
#pragma unroll
        for (int j = 0; j < 16; ++j) {
            float lo, hi; unpack2(acc1[j], lo, hi);
            __nv_bfloat162 b2 = __float22bfloat162_rn(make_float2(lo, hi));
            us[j] = *reinterpret_cast<unsigned*>(&b2);
        }
        uint4* outp = (uint4*)(g_projp + ((size_t)c * VOCAB + vb) * 16);
        outp[0] = make_uint4(us[0],  us[1],  us[2],  us[3]);
        outp[1] = make_uint4(us[4],  us[5],  us[6],  us[7]);
        outp[2] = make_uint4(us[8],  us[9],  us[10], us[11]);
        outp[3] = make_uint4(us[12], us[13], us[14], us[15]);
    }
}

// ---------------- kernel 2: finalize BN + tf32-round numeric W slice ----------------
__global__ __launch_bounds__(1024)
void k_finalize(const float* __restrict__ gamma_c, const float* __restrict__ beta_c,
                const float* __restrict__ gamma_r, const float* __restrict__ beta_r,
                const float* __restrict__ W) {
    int t = threadIdx.x;
    if (t < NC) {
        double m = g_sum_c[t] * (1.0 / (double)NCHILD);
        double v = g_ss_c[t] * (1.0 / (double)NCHILD) - m * m;
        float a = gamma_c[t] * rsqrtf((float)v + EPSBN);
        g_a_c[t] = a;
        g_s_c[t] = beta_c[t] - (float)m * a;
    }
    if (t < NR) {
        double m = g_sum_r[t] * (1.0 / (double)B_ROOT);
        double v = g_ss_r[t] * (1.0 / (double)B_ROOT) - m * m;
        float a = gamma_r[t] * rsqrtf((float)v + EPSBN);
        g_a_r[t] = a;
        g_s_r[t] = beta_r[t] - (float)m * a;
    }
    // g_wt[k][o] = tf32(W[o][CC*DIM + k])   (unfolded; BN applied to h instead)
    for (int i = t; i < NC * OUTD; i += 1024) {
        int k = i >> 5, o = i & 31;
        float w = W[(size_t)o * KDIM + CC * DIM + k];
        g_wt[i] = __uint_as_float(tf32r(w));
    }
}

// ---------------- kernel 3: big2 = child (tensor-core) ∪ root ----------------
__global__ __launch_bounds__(128, 3)
void k_big2(const int* __restrict__ cfi, const int* __restrict__ child_cat,
            const float* __restrict__ child_num,
            const int* __restrict__ idx, const int* __restrict__ root_cat,
            const float* __restrict__ root_num, const float* __restrict__ emb_root,
            const float* __restrict__ bias,
            float* __restrict__ out) {
    extern __shared__ float sm[];
    int bid = blockIdx.x;
    int t = threadIdx.x;
    int lane = t & 31;
    int warp = t >> 5;

    if (bid >= CH_BLKS) {
        // ---- root: one warp per root row ----
        int rr = (bid - CH_BLKS) * 4 + warp;
        int g = idx[rr];
        const int* cr = root_cat + (size_t)g * CR;
        float* orow = out + (size_t)rr * OUTCOLS;
#pragma unroll
        for (int c = 0; c < CR; ++c) {
            int v = cr[c];
            const float2* e = (const float2*)(emb_root + ((size_t)c * VOCAB + v) * DIM);
            *(float2*)(orow + c * DIM + lane * 2) = e[lane];
        }
        float2 x  = *(const float2*)(root_num + (size_t)g * NR + lane * 2);
        float2 a  = ((const float2*)g_a_r)[lane];
        float2 sh = ((const float2*)g_s_r)[lane];
        float2 y;
        y.x = fmaf(x.x, a.x, sh.x);
        y.y = fmaf(x.y, a.y, sh.y);
        *(float2*)(orow + CR * DIM + lane * 2) = y;
        return;
    }

    // ---- child: warp = one root (16 children) ----
    float* Wn_s = sm;                                    // [128][36]
    float* wb   = sm + WNS_FLOATS + warp * WARP_FLOATS;
    float* hs   = wb;                                    // [16][132] tf32 bits
    float* buf  = hs + 16 * 132;                         // [16][36]
    int*   cats = (int*)(buf + 16 * 36);                 // [16][16]
    int*   gs   = cats + 256;                            // [16]

    // block stage: Wn_s[k][o] (tf32 bits)
    for (int i = t; i < NC * OUTD; i += 128) {
        int k = i >> 5, o = i & 31;
        Wn_s[k * 36 + o] = g_wt[i];
    }
    __syncthreads();

    int root = bid * 4 + warp;
    if (lane < 16) gs[lane] = cfi[root * KFAN + lane];
    __syncwarp();

    // stage cats: 64 int4 tasks, 2 per lane
    {
        int t1 = lane, t2 = lane + 32;
        ((int4*)cats)[t1] = ((const int4*)(child_cat + (size_t)gs[t1 >> 2] * CC))[t1 & 3];
        ((int4*)cats)[t2] = ((const int4*)(child_cat + (size_t)gs[t2 >> 2] * CC))[t2 & 3];
    }

    // stage h: 16 rows, BN in fp32, round to tf32
    {
        float4 a4 = ((const float4*)g_a_c)[lane];
        float4 s4 = ((const float4*)g_s_c)[lane];
#pragma unroll 4
        for (int r = 0; r < 16; ++r) {
            float4 x = ((const float4*)(child_num + (size_t)gs[r] * NC))[lane];
            uint4 hv;
            hv.x = tf32r(fmaf(x.x, a4.x, s4.x));
            hv.y = tf32r(fmaf(x.y, a4.y, s4.y));
            hv.z = tf32r(fmaf(x.z, a4.z, s4.z));
            hv.w = tf32r(fmaf(x.w, a4.w, s4.w));
            *(uint4*)(hs + r * 132 + 4 * lane) = hv;
        }
    }

    // cooperative cat gather: lane handles (rA=lane>>2, m=lane&3) and (rB=rA+8, m)
    {
        float sA[8], sB[8];
#pragma unroll
        for (int j = 0; j < 8; ++j) { sA[j] = 0.f; sB[j] = 0.f; }
        int rA = lane >> 2, m = lane & 3;
        int rB = rA + 8;
#pragma unroll 2
        for (int c = 0; c < CC; ++c) {
            uint4 ua = ((const uint4*)(g_projp + ((size_t)c * VOCAB + cats[rA * 16 + c]) * 16))[m];
            uint4 ub = ((const uint4*)(g_projp + ((size_t)c * VOCAB + cats[rB * 16 + c]) * 16))[m];
            acc8(sA, ua);
            acc8(sB, ub);
        }
        *(float4*)(buf + rA * 36 + 8 * m)     = make_float4(sA[0], sA[1], sA[2], sA[3]);
        *(float4*)(buf + rA * 36 + 8 * m + 4) = make_float4(sA[4], sA[5], sA[6], sA[7]);
        *(float4*)(buf + rB * 36 + 8 * m)     = make_float4(sB[0], sB[1], sB[2], sB[3]);
        *(float4*)(buf + rB * 36 + 8 * m + 4) = make_float4(sB[4], sB[5], sB[6], sB[7]);
    }
    __syncwarp();

    // numeric GEMM: [16 x 128] @ [128 x 32] via mma.sync tf32
    float cfr[4][4];
#pragma unroll
    for (int nt = 0; nt < 4; ++nt)
#pragma unroll
        for (int j = 0; j < 4; ++j) cfr[nt][j] = 0.f;

    int gid = lane >> 2, tig = lane & 3;
#pragma unroll 4
    for (int kt = 0; kt < 16; ++kt) {
        int k0 = kt * 8;
        unsigned a0 = __float_as_uint(hs[gid * 132 + k0 + tig]);
        unsigned a1 = __float_as_uint(hs[(gid + 8) * 132 + k0 + tig]);
        unsigned a2 = __float_as_uint(hs[gid * 132 + k0 + tig + 4]);
        unsigned a3 = __float_as_uint(hs[(gid + 8) * 132 + k0 + tig + 4]);
#pragma unroll
        for (int nt = 0; nt < 4; ++nt) {
            unsigned b0 = __float_as_uint(Wn_s[(k0 + tig) * 36 + nt * 8 + gid]);
            unsigned b1 = __float_as_uint(Wn_s[(k0 + tig + 4) * 36 + nt * 8 + gid]);
            mma_tf32(cfr[nt][0], cfr[nt][1], cfr[nt][2], cfr[nt][3],
                     a0, a1, a2, a3, b0, b1);
        }
    }

    // add MMA result into buf (unique (r,o) owner per value)
#pragma unroll
    for (int nt = 0; nt < 4; ++nt) {
        int o0 = nt * 8 + 2 * tig;
        buf[gid * 36 + o0]           += cfr[nt][0];
        buf[gid * 36 + o0 + 1]       += cfr[nt][1];
        buf[(gid + 8) * 36 + o0]     += cfr[nt][2];
        buf[(gid + 8) * 36 + o0 + 1] += cfr[nt][3];
    }
    __syncwarp();

    // epilogue: lane = output column; relu + mean over 16 rows; coalesced store
    {
        float bp = __ldg(&bias[lane]);
        float acc = 0.f;
#pragma unroll
        for (int r = 0; r < 16; ++r)
            acc += fmaxf(buf[r * 36 + lane] + bp, 0.f);
        out[(size_t)root * OUTCOLS + CR * DIM + NR + lane] = acc * (1.0f / (float)KFAN);
    }
}

// ---------------- launch ----------------
extern "C" void kernel_launch(void* const* d_in, const int* in_sizes, int n_in,
                              void* d_out, int out_size) {
    const int *idx = nullptr, *cfi = nullptr, *root_cat = nullptr, *child_cat = nullptr;
    const float *root_num = nullptr, *child_num = nullptr;
    const float *emb_root = nullptr, *emb_child = nullptr;
    const float *W = nullptr, *bias = nullptr;
    const float *gamma_r = nullptr, *beta_r = nullptr, *gamma_c = nullptr, *beta_c = nullptr;

    for (int i = 0; i < n_in; ++i) {
        long long s = in_sizes[i];
        void* p = d_in[i];
        switch (s) {
            case 8192:      idx = (const int*)p; break;
            case 131072:    cfi = (const int*)p; break;
            case 1600000:   root_cat  = (const int*)p; break;
            case 8000000:   child_cat = (const int*)p; break;
            case 12800000:  root_num  = (const float*)p; break;
            case 64000000:  child_num = (const float*)p; break;
            case 25600000:  emb_root  = (const float*)p; break;
            case 51200000:  emb_child = (const float*)p; break;
            case 36864:     W = (const float*)p; break;
            case 32:        bias = (const float*)p; break;
            case 64:
                if (!gamma_r) gamma_r = (const float*)p; else beta_r = (const float*)p;
                break;
            case 128:
                if (!gamma_c) gamma_c = (const float*)p; else beta_c = (const float*)p;
                break;
            default: break;
        }
    }

    float* out = (float*)d_out;

    const int big1_smem = DIM * OUTD * (int)sizeof(float);   // 8192 B
    cudaFuncSetAttribute(k_big2, cudaFuncAttributeMaxDynamicSharedMemorySize, BIG2_SMEM);

    k_reset<<<1, 256>>>();
    k_big1<<<BIG1_BLKS, 256, big1_smem>>>(cfi, child_num, idx, root_num, emb_child, W);
    k_finalize<<<1, 1024>>>(gamma_c, beta_c, gamma_r, beta_r, W);
    k_big2<<<BIG2_BLKS, 128, BIG2_SMEM>>>(cfi, child_cat, child_num,
                                          idx, root_cat, root_num, emb_root, bias, out);
}

// round 11
// speedup vs baseline: 1.1723x; 1.1723x over previous
#include <cuda_runtime.h>
#include <cuda_bf16.h>
#include <cstdint>

#define B_ROOT   8192
#define KFAN     16
#define NCHILD   (B_ROOT * KFAN)     // 131072
#define VOCAB    50000
#define DIM      64
#define CR       8
#define NR       64
#define CC       16
#define NC       128
#define OUTD     32
#define KDIM     (CC * DIM + NC)     // 1152
#define OUTCOLS  (CR * DIM + NR + OUTD)  // 608
#define EPSBN    1e-5f

#define SC_BLKS   (NCHILD / 256)                    // 512
#define SR_BLKS   (B_ROOT / 128)                    // 64
#define PTILES    ((VOCAB + 127) / 128)             // 391 (128 vocab rows/block)
#define PROJ_BLKS (CC * PTILES)                     // 6256
#define BIG1_BLKS (SC_BLKS + SR_BLKS + PROJ_BLKS)   // 6832

#define CH_BLKS   (B_ROOT / 8)                      // 1024
#define RT_BLKS   (B_ROOT / 8)                      // 1024
#define BIG2_BLKS (CH_BLKS + RT_BLKS)               // 2048

// big1 proj smem: Ws[64][40] + 8 warps * As[16][68]
#define WS_FLOATS   (DIM * 40)                      // 2560
#define AS_FLOATS   (16 * 68)                       // 1088
#define BIG1_SMEM   ((WS_FLOATS + 8 * AS_FLOATS) * 4)   // 45056 B

// ---------------- scratch (device globals; allocation-free) ----------------
__device__ __align__(16) double g_sum_c[NC];
__device__ __align__(16) double g_ss_c [NC];
__device__ __align__(16) double g_sum_r[NR];
__device__ __align__(16) double g_ss_r [NR];
__device__ __align__(16) float g_a_c[NC];
__device__ __align__(16) float g_s_c[NC];
__device__ __align__(16) float g_a_r[NR];
__device__ __align__(16) float g_s_r[NR];
__device__ __align__(16) float g_wn[NC * OUTD];   // BN-folded numeric weight [k][o]
__device__ __align__(16) float g_bp[OUTD];        // bias + shift @ Wn^T
// bf16-packed categorical projection: 16 bf16x2 words per (c,v) row = 64 B
__device__ __align__(256) unsigned g_projp[CC * VOCAB * (OUTD / 2)];   // 51.2 MB

// ---------------- helpers ----------------
__device__ __forceinline__ unsigned long long pack2(float a, float b) {
    unsigned long long r;
    asm("mov.b64 %0, {%1, %2};" : "=l"(r) : "f"(a), "f"(b));
    return r;
}
__device__ __forceinline__ void unpack2(unsigned long long v, float& lo, float& hi) {
    asm("mov.b64 {%0, %1}, %2;" : "=f"(lo), "=f"(hi) : "l"(v));
}
__device__ __forceinline__ void fma2(unsigned long long& d, unsigned long long a, unsigned long long b) {
    asm("fma.rn.f32x2 %0, %1, %2, %0;" : "+l"(d) : "l"(a), "l"(b));
}
__device__ __forceinline__ void add2(unsigned long long& d, unsigned long long a) {
    asm("add.rn.f32x2 %0, %0, %1;" : "+l"(d) : "l"(a));
}
__device__ __forceinline__ unsigned tf32r(float x) {
    unsigned u;
    asm("cvt.rna.tf32.f32 %0, %1;" : "=r"(u) : "f"(x));
    return u;
}
__device__ __forceinline__ void mma_tf32(float& d0, float& d1, float& d2, float& d3,
                                         unsigned a0, unsigned a1, unsigned a2, unsigned a3,
                                         unsigned b0, unsigned b1) {
    asm volatile("mma.sync.aligned.m16n8k8.row.col.f32.tf32.tf32.f32 "
        "{%0,%1,%2,%3}, {%4,%5,%6,%7}, {%8,%9}, {%0,%1,%2,%3};"
        : "+f"(d0), "+f"(d1), "+f"(d2), "+f"(d3)
        : "r"(a0), "r"(a1), "r"(a2), "r"(a3), "r"(b0), "r"(b1));
}
// accumulate a uint4 of bf16x2 (8 outputs) into 8 fp32 accs
__device__ __forceinline__ void acc8(float* s, uint4 u) {
    unsigned w[4] = {u.x, u.y, u.z, u.w};
#pragma unroll
    for (int j = 0; j < 4; ++j) {
        __nv_bfloat162 b2 = *reinterpret_cast<__nv_bfloat162*>(&w[j]);
        float2 f = __bfloat1622float2(b2);
        s[2 * j]     += f.x;
        s[2 * j + 1] += f.y;
    }
}

// ---------------- kernel 0: reset ----------------
__global__ void k_reset() {
    int t = threadIdx.x;
    if (t < NC) { g_sum_c[t] = 0.0; g_ss_c[t] = 0.0; }
    if (t < NR) { g_sum_r[t] = 0.0; g_ss_r[t] = 0.0; }
}

// ---------------- kernel 1: big1 = stats_child ∪ stats_root ∪ proj(mma) ----------------
__global__ __launch_bounds__(256)
void k_big1(const int* __restrict__ cfi, const float* __restrict__ child_num,
            const int* __restrict__ idx, const float* __restrict__ root_num,
            const float* __restrict__ emb_child, const float* __restrict__ W) {
    extern __shared__ float sm[];
    int bid = blockIdx.x;
    int t = threadIdx.x;
    int lane = t & 31;
    int warp = t >> 5;

    if (bid < SC_BLKS) {
        int* rid = (int*)sm;
        rid[t] = cfi[bid * 256 + t];
        __syncthreads();
        int col = t & 127;
        int r0 = (t >> 7) * 128;
        float s[8], ss[8];
#pragma unroll
        for (int u = 0; u < 8; ++u) { s[u] = 0.f; ss[u] = 0.f; }
        for (int r = r0; r < r0 + 128; r += 8) {
            float x[8];
#pragma unroll
            for (int u = 0; u < 8; ++u) {
                int g = rid[r + u];
                x[u] = __ldg(&child_num[(size_t)g * NC + col]);
            }
#pragma unroll
            for (int u = 0; u < 8; ++u) { s[u] += x[u]; ss[u] += x[u] * x[u]; }
        }
        float st  = (s[0]+s[1])+(s[2]+s[3])+((s[4]+s[5])+(s[6]+s[7]));
        float sst = (ss[0]+ss[1])+(ss[2]+ss[3])+((ss[4]+ss[5])+(ss[6]+ss[7]));
        atomicAdd(&g_sum_c[col], (double)st);
        atomicAdd(&g_ss_c[col],  (double)sst);
        return;
    }
    if (bid < SC_BLKS + SR_BLKS) {
        int b = bid - SC_BLKS;
        int* rid = (int*)sm;
        if (t < 128) rid[t] = idx[b * 128 + t];
        __syncthreads();
        int col = t & 63;
        int r0 = (t >> 6) * 32;
        float s[4], ss[4];
#pragma unroll
        for (int u = 0; u < 4; ++u) { s[u] = 0.f; ss[u] = 0.f; }
        for (int r = r0; r < r0 + 32; r += 4) {
            float x[4];
#pragma unroll
            for (int u = 0; u < 4; ++u) {
                int g = rid[r + u];
                x[u] = __ldg(&root_num[(size_t)g * NR + col]);
            }
#pragma unroll
            for (int u = 0; u < 4; ++u) { s[u] += x[u]; ss[u] += x[u] * x[u]; }
        }
        atomicAdd(&g_sum_r[col], (double)((s[0]+s[1])+(s[2]+s[3])));
        atomicAdd(&g_ss_r[col],  (double)((ss[0]+ss[1])+(ss[2]+ss[3])));
        return;
    }

    // ---- proj via mma tf32: block = (c, 128 vocab rows); warp = 16 rows ----
    int pb = bid - (SC_BLKS + SR_BLKS);
    int c  = pb / PTILES;
    int vbase = (pb % PTILES) * 128;

    float* Ws = sm;                               // [64][40] tf32 bits
    float* As = sm + WS_FLOATS + warp * AS_FLOATS;// [16][68] tf32 bits

    // stage W slice (tf32): Ws[d][o], pitch 40
    for (int i = t; i < DIM * OUTD; i += 256) {
        int o = i >> 6, d = i & 63;
        Ws[d * 40 + o] = __uint_as_float(tf32r(W[(size_t)o * KDIM + c * DIM + d]));
    }
    __syncthreads();

    int v0w = vbase + warp * 16;
    // stage 16 emb rows (tf32) into As: 2 rows per iteration, coalesced
    {
        int rsel = lane >> 4;              // 0 or 1
        int col  = (lane & 15) * 4;
#pragma unroll
        for (int rr = 0; rr < 8; ++rr) {
            int row = 2 * rr + rsel;
            int v = v0w + row;
            float4 e = make_float4(0.f, 0.f, 0.f, 0.f);
            if (v < VOCAB)
                e = *(const float4*)(emb_child + ((size_t)c * VOCAB + v) * DIM + col);
            float4 a;
            a.x = __uint_as_float(tf32r(e.x));
            a.y = __uint_as_float(tf32r(e.y));
            a.z = __uint_as_float(tf32r(e.z));
            a.w = __uint_as_float(tf32r(e.w));
            *(float4*)(As + row * 68 + col) = a;
        }
    }
    __syncwarp();

    // GEMM [16 x 64] @ [64 x 32]
    float cfr[4][4];
#pragma unroll
    for (int nt = 0; nt < 4; ++nt)
#pragma unroll
        for (int j = 0; j < 4; ++j) cfr[nt][j] = 0.f;

    int gid = lane >> 2, tig = lane & 3;
#pragma unroll
    for (int kt = 0; kt < 8; ++kt) {
        int k0 = kt * 8;
        unsigned a0 = __float_as_uint(As[gid * 68 + k0 + tig]);
        unsigned a1 = __float_as_uint(As[(gid + 8) * 68 + k0 + tig]);
        unsigned a2 = __float_as_uint(As[gid * 68 + k0 + tig + 4]);
        unsigned a3 = __float_as_uint(As[(gid + 8) * 68 + k0 + tig + 4]);
#pragma unroll
        for (int nt = 0; nt < 4; ++nt) {
            unsigned b0 = __float_as_uint(Ws[(k0 + tig) * 40 + nt * 8 + gid]);
            unsigned b1 = __float_as_uint(Ws[(k0 + tig + 4) * 40 + nt * 8 + gid]);
            mma_tf32(cfr[nt][0], cfr[nt][1], cfr[nt][2], cfr[nt][3],
                     a0, a1, a2, a3, b0, b1);
        }
    }

    // epilogue: pack bf16x2, store. lane owns cols (nt*8+2tig, +1) rows gid, gid+8
    int vA = v0w + gid, vB = vA + 8;
#pragma unroll
    for (int nt = 0; nt < 4; ++nt) {
        int word = nt * 4 + tig;
        if (vA < VOCAB) {
            __nv_bfloat162 b2 = __float22bfloat162_rn(make_float2(cfr[nt][0], cfr[nt][1]));
            g_projp[((size_t)c * VOCAB + vA) * 16 + word] = *reinterpret_cast<unsigned*>(&b2);
        }
        if (vB < VOCAB) {
            __nv_bfloat162 b2 = __float22bfloat162_rn(make_float2(cfr[nt][2], cfr[nt][3]));
            g_projp[((size_t)c * VOCAB + vB) * 16 + word] = *reinterpret_cast<unsigned*>(&b2);
        }
    }
}

// ---------------- kernel 2: finalize BN + fold numeric weights ----------------
__global__ __launch_bounds__(1024)
void k_finalize(const float* __restrict__ gamma_c, const float* __restrict__ beta_c,
                const float* __restrict__ gamma_r, const float* __restrict__ beta_r,
                const float* __restrict__ W, const float* __restrict__ bias) {
    int t = threadIdx.x;
    if (t < NC) {
        double m = g_sum_c[t] * (1.0 / (double)NCHILD);
        double v = g_ss_c[t] * (1.0 / (double)NCHILD) - m * m;
        float a = gamma_c[t] * rsqrtf((float)v + EPSBN);
        g_a_c[t] = a;
        g_s_c[t] = beta_c[t] - (float)m * a;
    }
    if (t < NR) {
        double m = g_sum_r[t] * (1.0 / (double)B_ROOT);
        double v = g_ss_r[t] * (1.0 / (double)B_ROOT) - m * m;
        float a = gamma_r[t] * rsqrtf((float)v + EPSBN);
        g_a_r[t] = a;
        g_s_r[t] = beta_r[t] - (float)m * a;
    }
    __syncthreads();
    for (int i = t; i < NC * OUTD; i += 1024) {
        int k = i >> 5, o = i & 31;
        g_wn[i] = g_a_c[k] * W[(size_t)o * KDIM + CC * DIM + k];
    }
    if (t < 128) {
        int o = t >> 2;
        int sl = t & 3;
        const float* wrow = W + (size_t)o * KDIM + CC * DIM;
        float a0 = 0.f, a1 = 0.f, a2 = 0.f, a3 = 0.f;
#pragma unroll
        for (int j = 0; j < 8; ++j) {
            a0 += g_s_c[sl + 16 * j +  0] * wrow[sl + 16 * j +  0];
            a1 += g_s_c[sl + 16 * j +  4] * wrow[sl + 16 * j +  4];
            a2 += g_s_c[sl + 16 * j +  8] * wrow[sl + 16 * j +  8];
            a3 += g_s_c[sl + 16 * j + 12] * wrow[sl + 16 * j + 12];
        }
        float acc = (a0 + a1) + (a2 + a3);
        acc += __shfl_xor_sync(0xffffffffu, acc, 1);
        acc += __shfl_xor_sync(0xffffffffu, acc, 2);
        if (sl == 0) g_bp[o] = acc + bias[o];
    }
}

// ---------------- kernel 3: big2 = child (coop gather + split-half FFMA) ∪ root ------
__global__ __launch_bounds__(256, 2)
void k_big2(const int* __restrict__ cfi, const int* __restrict__ child_cat,
            const float* __restrict__ child_num,
            const int* __restrict__ idx, const int* __restrict__ root_cat,
            const float* __restrict__ root_num, const float* __restrict__ emb_root,
            float* __restrict__ out) {
    extern __shared__ float sm[];
    int bid = blockIdx.x;
    int t = threadIdx.x;
    int lane = t & 31;

    if (bid >= CH_BLKS) {
        // ---- root part: one warp per root row ----
        int rr = (bid - CH_BLKS) * 8 + (t >> 5);
        int g = idx[rr];
        const int* cr = root_cat + (size_t)g * CR;
        float* orow = out + (size_t)rr * OUTCOLS;
#pragma unroll
        for (int c = 0; c < CR; ++c) {
            int v = cr[c];
            const float2* e = (const float2*)(emb_root + ((size_t)c * VOCAB + v) * DIM);
            *(float2*)(orow + c * DIM + lane * 2) = e[lane];
        }
        float2 x  = *(const float2*)(root_num + (size_t)g * NR + lane * 2);
        float2 a  = ((const float2*)g_a_r)[lane];
        float2 sh = ((const float2*)g_s_r)[lane];
        float2 y;
        y.x = fmaf(x.x, a.x, sh.x);
        y.y = fmaf(x.y, a.y, sh.y);
        *(float2*)(orow + CR * DIM + lane * 2) = y;
        return;
    }

    // ---- child part: warp = 16 rows (one root) x 2 half-threads ----
    float* Wn = sm;   // [NC][OUTD] = 16 KB
    for (int i = t; i < NC * OUTD; i += 256)
        Wn[i] = g_wn[i];
    __syncthreads();

    int warp  = t >> 5;
    int sub   = lane & 15;          // row within root
    int half  = lane >> 4;          // k-half AND out-chunk owner
    int root  = bid * 8 + warp;
    int row   = root * KFAN + sub;
    int g     = cfi[row];

    unsigned long long acc[16];
#pragma unroll
    for (int p = 0; p < 16; ++p) {
        if (half == 0) {
            float2 bb = ((const float2*)g_bp)[p];
            acc[p] = pack2(bb.x, bb.y);
        } else {
            acc[p] = pack2(0.f, 0.f);
        }
    }

    // all 16 categorical indices for THIS row (both half-lanes load; L1 dedups)
    int cats[CC];
    {
        const int4* crow4 = (const int4*)(child_cat + (size_t)g * CC);
#pragma unroll
        for (int q = 0; q < 4; ++q) {
            int4 c4 = crow4[q];
            cats[4 * q + 0] = c4.x;
            cats[4 * q + 1] = c4.y;
            cats[4 * q + 2] = c4.z;
            cats[4 * q + 3] = c4.w;
        }
    }

    // cooperative cat gather: lane (sub, half) loads 32B = outs [half*16, half*16+16)
    // per warp-instruction: 16 rows x one line each (64B row within one 128B line)
    float s[16];
#pragma unroll
    for (int j = 0; j < 16; ++j) s[j] = 0.f;
    {
        const uint4* p0 = (const uint4*)(g_projp + ((size_t)0 * VOCAB + cats[0]) * 16) + half * 2;
        uint4 qa = p0[0], qb = p0[1];
#pragma unroll
        for (int c = 0; c < CC; ++c) {
            uint4 na, nb;
            if (c + 1 < CC) {
                const uint4* pn = (const uint4*)(g_projp + ((size_t)(c + 1) * VOCAB + cats[c + 1]) * 16) + half * 2;
                na = pn[0]; nb = pn[1];
            }
            acc8(s, qa);
            acc8(s + 8, qb);
            qa = na; qb = nb;
        }
    }

    // numeric: 64 k-values for this half (FFMA2, Wn broadcast LDS)
    {
        const float4* nrow = (const float4*)(child_num + (size_t)g * NC + half * 64);
#pragma unroll 4
        for (int j = 0; j < 16; ++j) {
            float4 x = nrow[j];
            const float h[4] = {x.x, x.y, x.z, x.w};
            int kb = half * 64 + j * 4;
#pragma unroll
            for (int q = 0; q < 4; ++q) {
                unsigned long long hh = pack2(h[q], h[q]);
                const ulonglong2* wrow = (const ulonglong2*)(Wn + (kb + q) * OUTD);
#pragma unroll
                for (int p = 0; p < 8; ++p) {
                    ulonglong2 w = wrow[p];
                    fma2(acc[2 * p],     hh, w.x);
                    fma2(acc[2 * p + 1], hh, w.y);
                }
            }
        }
    }

    // merge cat partials: this lane owns outs [half*16, half*16+16) -> acc[half*8 + jj]
#pragma unroll
    for (int jj = 0; jj < 8; ++jj)
        add2(acc[half * 8 + jj], pack2(s[2 * jj], s[2 * jj + 1]));

    // combine halves (xor 16), ReLU, then 16-row mean (xor 1,2,4,8)
    float r[32];
#pragma unroll
    for (int p = 0; p < 16; ++p) {
        float lo, hi;
        unpack2(acc[p], lo, hi);
        r[2 * p] = lo; r[2 * p + 1] = hi;
    }
#pragma unroll
    for (int i = 0; i < 32; ++i) {
        r[i] += __shfl_xor_sync(0xffffffffu, r[i], 16);   // full row value
        r[i] = fmaxf(r[i], 0.f);                          // ReLU
    }
#pragma unroll
    for (int sh = 1; sh < 16; sh <<= 1) {
#pragma unroll
        for (int i = 0; i < 32; ++i)
            r[i] += __shfl_xor_sync(0xffffffffu, r[i], sh);
    }
    if (half == 0) {
        float2 val;
        val.x = r[2 * sub]     * (1.0f / (float)KFAN);
        val.y = r[2 * sub + 1] * (1.0f / (float)KFAN);
        *(float2*)(out + (size_t)root * OUTCOLS + CR * DIM + NR + 2 * sub) = val;
    }
}

// ---------------- launch ----------------
extern "C" void kernel_launch(void* const* d_in, const int* in_sizes, int n_in,
                              void* d_out, int out_size) {
    const int *idx = nullptr, *cfi = nullptr, *root_cat = nullptr, *child_cat = nullptr;
    const float *root_num = nullptr, *child_num = nullptr;
    const float *emb_root = nullptr, *emb_child = nullptr;
    const float *W = nullptr, *bias = nullptr;
    const float *gamma_r = nullptr, *beta_r = nullptr, *gamma_c = nullptr, *beta_c = nullptr;

    for (int i = 0; i < n_in; ++i) {
        long long s = in_sizes[i];
        void* p = d_in[i];
        switch (s) {
            case 8192:      idx = (const int*)p; break;
            case 131072:    cfi = (const int*)p; break;
            case 1600000:   root_cat  = (const int*)p; break;
            case 8000000:   child_cat = (const int*)p; break;
            case 12800000:  root_num  = (const float*)p; break;
            case 64000000:  child_num = (const float*)p; break;
            case 25600000:  emb_root  = (const float*)p; break;
            case 51200000:  emb_child = (const float*)p; break;
            case 36864:     W = (const float*)p; break;
            case 32:        bias = (const float*)p; break;
            case 64:
                if (!gamma_r) gamma_r = (const float*)p; else beta_r = (const float*)p;
                break;
            case 128:
                if (!gamma_c) gamma_c = (const float*)p; else beta_c = (const float*)p;
                break;
            default: break;
        }
    }

    float* out = (float*)d_out;

    cudaFuncSetAttribute(k_big1, cudaFuncAttributeMaxDynamicSharedMemorySize, BIG1_SMEM);
    const int big2_smem = NC * OUTD * (int)sizeof(float);    // 16384 B

    k_reset<<<1, 256>>>();
    k_big1<<<BIG1_BLKS, 256, BIG1_SMEM>>>(cfi, child_num, idx, root_num, emb_child, W);
    k_finalize<<<1, 1024>>>(gamma_c, beta_c, gamma_r, beta_r, W, bias);
    k_big2<<<BIG2_BLKS, 256, big2_smem>>>(cfi, child_cat, child_num,
                                          idx, root_cat, root_num, emb_root, out);
}

// round 12
// speedup vs baseline: 1.2677x; 1.0814x over previous
#include <cuda_runtime.h>
#include <cuda_bf16.h>
#include <cstdint>

#define B_ROOT   8192
#define KFAN     16
#define NCHILD   (B_ROOT * KFAN)     // 131072
#define VOCAB    50000
#define DIM      64
#define CR       8
#define NR       64
#define CC       16
#define NC       128
#define OUTD     32
#define KDIM     (CC * DIM + NC)     // 1152
#define OUTCOLS  (CR * DIM + NR + OUTD)  // 608
#define EPSBN    1e-5f

#define SC_BLKS   (NCHILD / 256)                    // 512
#define SR_BLKS   (B_ROOT / 128)                    // 64
#define PTILES    ((VOCAB + 127) / 128)             // 391 (128 vocab rows/block)
#define PROJ_BLKS (CC * PTILES)                     // 6256
#define BIG1_BLKS (SC_BLKS + SR_BLKS + PROJ_BLKS)   // 6832

#define CH_BLKS   (NCHILD / 128)                    // 1024 (2 threads per child row)
#define RT_BLKS   (B_ROOT / 8)                      // 1024
#define BIG2_BLKS (CH_BLKS + RT_BLKS)               // 2048

// big1 proj smem: Ws[64][40] + 8 warps * As[16][68]
#define WS_FLOATS   (DIM * 40)                      // 2560
#define AS_FLOATS   (16 * 68)                       // 1088
#define BIG1_SMEM   ((WS_FLOATS + 8 * AS_FLOATS) * 4)   // 45056 B

// ---------------- scratch (device globals; allocation-free) ----------------
__device__ __align__(16) double g_sum_c[NC];
__device__ __align__(16) double g_ss_c [NC];
__device__ __align__(16) double g_sum_r[NR];
__device__ __align__(16) double g_ss_r [NR];
__device__ __align__(16) float g_a_c[NC];
__device__ __align__(16) float g_s_c[NC];
__device__ __align__(16) float g_a_r[NR];
__device__ __align__(16) float g_s_r[NR];
__device__ __align__(16) float g_wn[NC * OUTD];   // BN-folded numeric weight [k][o]
__device__ __align__(16) float g_bp[OUTD];        // bias + shift @ Wn^T
// bf16-packed categorical projection: 16 bf16x2 words per (c,v) row = 64 B
__device__ __align__(256) unsigned g_projp[CC * VOCAB * (OUTD / 2)];   // 51.2 MB

// ---------------- helpers ----------------
__device__ __forceinline__ unsigned long long pack2(float a, float b) {
    unsigned long long r;
    asm("mov.b64 %0, {%1, %2};" : "=l"(r) : "f"(a), "f"(b));
    return r;
}
__device__ __forceinline__ void unpack2(unsigned long long v, float& lo, float& hi) {
    asm("mov.b64 {%0, %1}, %2;" : "=f"(lo), "=f"(hi) : "l"(v));
}
__device__ __forceinline__ void fma2(unsigned long long& d, unsigned long long a, unsigned long long b) {
    asm("fma.rn.f32x2 %0, %1, %2, %0;" : "+l"(d) : "l"(a), "l"(b));
}
__device__ __forceinline__ void add2(unsigned long long& d, unsigned long long a) {
    asm("add.rn.f32x2 %0, %0, %1;" : "+l"(d) : "l"(a));
}
__device__ __forceinline__ void addbf2(unsigned long long& d, unsigned w) {
    __nv_bfloat162 b2 = *reinterpret_cast<__nv_bfloat162*>(&w);
    float2 f = __bfloat1622float2(b2);
    add2(d, pack2(f.x, f.y));
}
__device__ __forceinline__ unsigned tf32r(float x) {
    unsigned u;
    asm("cvt.rna.tf32.f32 %0, %1;" : "=r"(u) : "f"(x));
    return u;
}
__device__ __forceinline__ void mma_tf32(float& d0, float& d1, float& d2, float& d3,
                                         unsigned a0, unsigned a1, unsigned a2, unsigned a3,
                                         unsigned b0, unsigned b1) {
    asm volatile("mma.sync.aligned.m16n8k8.row.col.f32.tf32.tf32.f32 "
        "{%0,%1,%2,%3}, {%4,%5,%6,%7}, {%8,%9}, {%0,%1,%2,%3};"
        : "+f"(d0), "+f"(d1), "+f"(d2), "+f"(d3)
        : "r"(a0), "r"(a1), "r"(a2), "r"(a3), "r"(b0), "r"(b1));
}

// ---------------- kernel 0: reset ----------------
__global__ void k_reset() {
    int t = threadIdx.x;
    if (t < NC) { g_sum_c[t] = 0.0; g_ss_c[t] = 0.0; }
    if (t < NR) { g_sum_r[t] = 0.0; g_ss_r[t] = 0.0; }
}

// ---------------- kernel 1: big1 = stats_child ∪ stats_root ∪ proj(mma) ----------------
__global__ __launch_bounds__(256)
void k_big1(const int* __restrict__ cfi, const float* __restrict__ child_num,
            const int* __restrict__ idx, const float* __restrict__ root_num,
            const float* __restrict__ emb_child, const float* __restrict__ W) {
    extern __shared__ float sm[];
    int bid = blockIdx.x;
    int t = threadIdx.x;
    int lane = t & 31;
    int warp = t >> 5;

    if (bid < SC_BLKS) {
        int* rid = (int*)sm;
        rid[t] = cfi[bid * 256 + t];
        __syncthreads();
        int col = t & 127;
        int r0 = (t >> 7) * 128;
        float s[8], ss[8];
#pragma unroll
        for (int u = 0; u < 8; ++u) { s[u] = 0.f; ss[u] = 0.f; }
        for (int r = r0; r < r0 + 128; r += 8) {
            float x[8];
#pragma unroll
            for (int u = 0; u < 8; ++u) {
                int g = rid[r + u];
                x[u] = __ldg(&child_num[(size_t)g * NC + col]);
            }
#pragma unroll
            for (int u = 0; u < 8; ++u) { s[u] += x[u]; ss[u] += x[u] * x[u]; }
        }
        float st  = (s[0]+s[1])+(s[2]+s[3])+((s[4]+s[5])+(s[6]+s[7]));
        float sst = (ss[0]+ss[1])+(ss[2]+ss[3])+((ss[4]+ss[5])+(ss[6]+ss[7]));
        atomicAdd(&g_sum_c[col], (double)st);
        atomicAdd(&g_ss_c[col],  (double)sst);
        return;
    }
    if (bid < SC_BLKS + SR_BLKS) {
        int b = bid - SC_BLKS;
        int* rid = (int*)sm;
        if (t < 128) rid[t] = idx[b * 128 + t];
        __syncthreads();
        int col = t & 63;
        int r0 = (t >> 6) * 32;
        float s[4], ss[4];
#pragma unroll
        for (int u = 0; u < 4; ++u) { s[u] = 0.f; ss[u] = 0.f; }
        for (int r = r0; r < r0 + 32; r += 4) {
            float x[4];
#pragma unroll
            for (int u = 0; u < 4; ++u) {
                int g = rid[r + u];
                x[u] = __ldg(&root_num[(size_t)g * NR + col]);
            }
#pragma unroll
            for (int u = 0; u < 4; ++u) { s[u] += x[u]; ss[u] += x[u] * x[u]; }
        }
        atomicAdd(&g_sum_r[col], (double)((s[0]+s[1])+(s[2]+s[3])));
        atomicAdd(&g_ss_r[col],  (double)((ss[0]+ss[1])+(ss[2]+ss[3])));
        return;
    }

    // ---- proj via mma tf32: block = (c, 128 vocab rows); warp = 16 rows ----
    int pb = bid - (SC_BLKS + SR_BLKS);
    int c  = pb / PTILES;
    int vbase = (pb % PTILES) * 128;

    float* Ws = sm;                               // [64][40] tf32 bits
    float* As = sm + WS_FLOATS + warp * AS_FLOATS;// [16][68] tf32 bits

    for (int i = t; i < DIM * OUTD; i += 256) {
        int o = i >> 6, d = i & 63;
        Ws[d * 40 + o] = __uint_as_float(tf32r(W[(size_t)o * KDIM + c * DIM + d]));
    }
    __syncthreads();

    int v0w = vbase + warp * 16;
    {
        int rsel = lane >> 4;
        int col  = (lane & 15) * 4;
#pragma unroll
        for (int rr = 0; rr < 8; ++rr) {
            int row = 2 * rr + rsel;
            int v = v0w + row;
            float4 e = make_float4(0.f, 0.f, 0.f, 0.f);
            if (v < VOCAB)
                e = *(const float4*)(emb_child + ((size_t)c * VOCAB + v) * DIM + col);
            float4 a;
            a.x = __uint_as_float(tf32r(e.x));
            a.y = __uint_as_float(tf32r(e.y));
            a.z = __uint_as_float(tf32r(e.z));
            a.w = __uint_as_float(tf32r(e.w));
            *(float4*)(As + row * 68 + col) = a;
        }
    }
    __syncwarp();

    float cfr[4][4];
#pragma unroll
    for (int nt = 0; nt < 4; ++nt)
#pragma unroll
        for (int j = 0; j < 4; ++j) cfr[nt][j] = 0.f;

    int gid = lane >> 2, tig = lane & 3;
#pragma unroll
    for (int kt = 0; kt < 8; ++kt) {
        int k0 = kt * 8;
        unsigned a0 = __float_as_uint(As[gid * 68 + k0 + tig]);
        unsigned a1 = __float_as_uint(As[(gid + 8) * 68 + k0 + tig]);
        unsigned a2 = __float_as_uint(As[gid * 68 + k0 + tig + 4]);
        unsigned a3 = __float_as_uint(As[(gid + 8) * 68 + k0 + tig + 4]);
#pragma unroll
        for (int nt = 0; nt < 4; ++nt) {
            unsigned b0 = __float_as_uint(Ws[(k0 + tig) * 40 + nt * 8 + gid]);
            unsigned b1 = __float_as_uint(Ws[(k0 + tig + 4) * 40 + nt * 8 + gid]);
            mma_tf32(cfr[nt][0], cfr[nt][1], cfr[nt][2], cfr[nt][3],
                     a0, a1, a2, a3, b0, b1);
        }
    }

    int vA = v0w + gid, vB = vA + 8;
#pragma unroll
    for (int nt = 0; nt < 4; ++nt) {
        int word = nt * 4 + tig;
        if (vA < VOCAB) {
            __nv_bfloat162 b2 = __float22bfloat162_rn(make_float2(cfr[nt][0], cfr[nt][1]));
            g_projp[((size_t)c * VOCAB + vA) * 16 + word] = *reinterpret_cast<unsigned*>(&b2);
        }
        if (vB < VOCAB) {
            __nv_bfloat162 b2 = __float22bfloat162_rn(make_float2(cfr[nt][2], cfr[nt][3]));
            g_projp[((size_t)c * VOCAB + vB) * 16 + word] = *reinterpret_cast<unsigned*>(&b2);
        }
    }
}

// ---------------- kernel 2: finalize BN + fold numeric weights ----------------
__global__ __launch_bounds__(1024)
void k_finalize(const float* __restrict__ gamma_c, const float* __restrict__ beta_c,
                const float* __restrict__ gamma_r, const float* __restrict__ beta_r,
                const float* __restrict__ W, const float* __restrict__ bias) {
    int t = threadIdx.x;
    if (t < NC) {
        double m = g_sum_c[t] * (1.0 / (double)NCHILD);
        double v = g_ss_c[t] * (1.0 / (double)NCHILD) - m * m;
        float a = gamma_c[t] * rsqrtf((float)v + EPSBN);
        g_a_c[t] = a;
        g_s_c[t] = beta_c[t] - (float)m * a;
    }
    if (t < NR) {
        double m = g_sum_r[t] * (1.0 / (double)B_ROOT);
        double v = g_ss_r[t] * (1.0 / (double)B_ROOT) - m * m;
        float a = gamma_r[t] * rsqrtf((float)v + EPSBN);
        g_a_r[t] = a;
        g_s_r[t] = beta_r[t] - (float)m * a;
    }
    __syncthreads();
    for (int i = t; i < NC * OUTD; i += 1024) {
        int k = i >> 5, o = i & 31;
        g_wn[i] = g_a_c[k] * W[(size_t)o * KDIM + CC * DIM + k];
    }
    if (t < 128) {
        int o = t >> 2;
        int sl = t & 3;
        const float* wrow = W + (size_t)o * KDIM + CC * DIM;
        float a0 = 0.f, a1 = 0.f, a2 = 0.f, a3 = 0.f;
#pragma unroll
        for (int j = 0; j < 8; ++j) {
            a0 += g_s_c[sl + 16 * j +  0] * wrow[sl + 16 * j +  0];
            a1 += g_s_c[sl + 16 * j +  4] * wrow[sl + 16 * j +  4];
            a2 += g_s_c[sl + 16 * j +  8] * wrow[sl + 16 * j +  8];
            a3 += g_s_c[sl + 16 * j + 12] * wrow[sl + 16 * j + 12];
        }
        float acc = (a0 + a1) + (a2 + a3);
        acc += __shfl_xor_sync(0xffffffffu, acc, 1);
        acc += __shfl_xor_sync(0xffffffffu, acc, 2);
        if (sl == 0) g_bp[o] = acc + bias[o];
    }
}

// ---------------- kernel 3: big2 = child (2 threads/row, R9-proven) ∪ root ----------------
__global__ __launch_bounds__(256, 2)
void k_big2(const int* __restrict__ cfi, const int* __restrict__ child_cat,
            const float* __restrict__ child_num,
            const int* __restrict__ idx, const int* __restrict__ root_cat,
            const float* __restrict__ root_num, const float* __restrict__ emb_root,
            float* __restrict__ out) {
    extern __shared__ float sm[];
    int bid = blockIdx.x;
    int t = threadIdx.x;
    int lane = t & 31;

    if (bid >= CH_BLKS) {
        // ---- root part: one warp per root row ----
        int warp = (bid - CH_BLKS) * 8 + (t >> 5);
        int g = idx[warp];
        const int* cr = root_cat + (size_t)g * CR;
        float* orow = out + (size_t)warp * OUTCOLS;
#pragma unroll
        for (int c = 0; c < CR; ++c) {
            int v = cr[c];
            const float2* e = (const float2*)(emb_root + ((size_t)c * VOCAB + v) * DIM);
            *(float2*)(orow + c * DIM + lane * 2) = e[lane];
        }
        float2 x  = *(const float2*)(root_num + (size_t)g * NR + lane * 2);
        float2 a  = ((const float2*)g_a_r)[lane];
        float2 sh = ((const float2*)g_s_r)[lane];
        float2 y;
        y.x = fmaf(x.x, a.x, sh.x);
        y.y = fmaf(x.y, a.y, sh.y);
        *(float2*)(orow + CR * DIM + lane * 2) = y;
        return;
    }

    // ---- child part: warp = 16 rows (one root) x 2 half-threads ----
    float* Wn = sm;   // [NC][OUTD] = 16 KB
    for (int i = t; i < NC * OUTD; i += 256)
        Wn[i] = g_wn[i];
    __syncthreads();

    int warp  = t >> 5;
    int sub   = lane & 15;          // row within root
    int half  = lane >> 4;          // 0: cats 0-7 / k 0-63; 1: cats 8-15 / k 64-127
    int root  = bid * 8 + warp;
    int row   = root * KFAN + sub;
    int g     = cfi[row];

    unsigned long long acc[16];
#pragma unroll
    for (int p = 0; p < 16; ++p) {
        if (half == 0) {
            float2 bb = ((const float2*)g_bp)[p];
            acc[p] = pack2(bb.x, bb.y);
        } else {
            acc[p] = pack2(0.f, 0.f);
        }
    }

    // 8 categorical columns for this half
    int cats[8];
    {
        const int4* crow4 = (const int4*)(child_cat + (size_t)g * CC) + half * 2;
        int4 c0 = crow4[0], c1 = crow4[1];
        cats[0] = c0.x; cats[1] = c0.y; cats[2] = c0.z; cats[3] = c0.w;
        cats[4] = c1.x; cats[5] = c1.y; cats[6] = c1.z; cats[7] = c1.w;
    }
    int cbase = half * 8;

    // cat gathers with 1-row lookahead (4 uint4 in flight + next 4)
    {
        const uint4* pp = (const uint4*)(g_projp + ((size_t)cbase * VOCAB + cats[0]) * 16);
        uint4 q0 = pp[0], q1 = pp[1], q2 = pp[2], q3 = pp[3];
#pragma unroll
        for (int c = 0; c < 8; ++c) {
            uint4 n0, n1, n2, n3;
            if (c + 1 < 8) {
                const uint4* pn = (const uint4*)(g_projp + ((size_t)(cbase + c + 1) * VOCAB + cats[c + 1]) * 16);
                n0 = pn[0]; n1 = pn[1]; n2 = pn[2]; n3 = pn[3];
            }
            addbf2(acc[0],  q0.x); addbf2(acc[1],  q0.y);
            addbf2(acc[2],  q0.z); addbf2(acc[3],  q0.w);
            addbf2(acc[4],  q1.x); addbf2(acc[5],  q1.y);
            addbf2(acc[6],  q1.z); addbf2(acc[7],  q1.w);
            addbf2(acc[8],  q2.x); addbf2(acc[9],  q2.y);
            addbf2(acc[10], q2.z); addbf2(acc[11], q2.w);
            addbf2(acc[12], q3.x); addbf2(acc[13], q3.y);
            addbf2(acc[14], q3.z); addbf2(acc[15], q3.w);
            q0 = n0; q1 = n1; q2 = n2; q3 = n3;
        }
    }

    // numeric: 64 k-values for this half
    {
        const float4* nrow = (const float4*)(child_num + (size_t)g * NC + half * 64);
#pragma unroll 4
        for (int j = 0; j < 16; ++j) {
            float4 x = nrow[j];
            const float h[4] = {x.x, x.y, x.z, x.w};
            int kb = half * 64 + j * 4;
#pragma unroll
            for (int q = 0; q < 4; ++q) {
                unsigned long long hh = pack2(h[q], h[q]);
                const ulonglong2* wrow = (const ulonglong2*)(Wn + (kb + q) * OUTD);
#pragma unroll
                for (int p = 0; p < 8; ++p) {
                    ulonglong2 w = wrow[p];
                    fma2(acc[2 * p],     hh, w.x);
                    fma2(acc[2 * p + 1], hh, w.y);
                }
            }
        }
    }

    // combine halves (xor 16), ReLU, then 16-row mean (xor 1,2,4,8)
    float r[32];
#pragma unroll
    for (int p = 0; p < 16; ++p) {
        float lo, hi;
        unpack2(acc[p], lo, hi);
        r[2 * p] = lo; r[2 * p + 1] = hi;
    }
#pragma unroll
    for (int i = 0; i < 32; ++i) {
        r[i] += __shfl_xor_sync(0xffffffffu, r[i], 16);   // full row value
        r[i] = fmaxf(r[i], 0.f);                          // ReLU
    }
#pragma unroll
    for (int s = 1; s < 16; s <<= 1) {
#pragma unroll
        for (int i = 0; i < 32; ++i)
            r[i] += __shfl_xor_sync(0xffffffffu, r[i], s);
    }
    if (half == 0) {
        float2 val;
        val.x = r[2 * sub]     * (1.0f / (float)KFAN);
        val.y = r[2 * sub + 1] * (1.0f / (float)KFAN);
        *(float2*)(out + (size_t)root * OUTCOLS + CR * DIM + NR + 2 * sub) = val;
    }
}

// ---------------- launch ----------------
extern "C" void kernel_launch(void* const* d_in, const int* in_sizes, int n_in,
                              void* d_out, int out_size) {
    const int *idx = nullptr, *cfi = nullptr, *root_cat = nullptr, *child_cat = nullptr;
    const float *root_num = nullptr, *child_num = nullptr;
    const float *emb_root = nullptr, *emb_child = nullptr;
    const float *W = nullptr, *bias = nullptr;
    const float *gamma_r = nullptr, *beta_r = nullptr, *gamma_c = nullptr, *beta_c = nullptr;

    for (int i = 0; i < n_in; ++i) {
        long long s = in_sizes[i];
        void* p = d_in[i];
        switch (s) {
            case 8192:      idx = (const int*)p; break;
            case 131072:    cfi = (const int*)p; break;
            case 1600000:   root_cat  = (const int*)p; break;
            case 8000000:   child_cat = (const int*)p; break;
            case 12800000:  root_num  = (const float*)p; break;
            case 64000000:  child_num = (const float*)p; break;
            case 25600000:  emb_root  = (const float*)p; break;
            case 51200000:  emb_child = (const float*)p; break;
            case 36864:     W = (const float*)p; break;
            case 32:        bias = (const float*)p; break;
            case 64:
                if (!gamma_r) gamma_r = (const float*)p; else beta_r = (const float*)p;
                break;
            case 128:
                if (!gamma_c) gamma_c = (const float*)p; else beta_c = (const float*)p;
                break;
            default: break;
        }
    }

    float* out = (float*)d_out;

    cudaFuncSetAttribute(k_big1, cudaFuncAttributeMaxDynamicSharedMemorySize, BIG1_SMEM);
    const int big2_smem = NC * OUTD * (int)sizeof(float);    // 16384 B

    k_reset<<<1, 256>>>();
    k_big1<<<BIG1_BLKS, 256, BIG1_SMEM>>>(cfi, child_num, idx, root_num, emb_child, W);
    k_finalize<<<1, 1024>>>(gamma_c, beta_c, gamma_r, beta_r, W, bias);
    k_big2<<<BIG2_BLKS, 256, big2_smem>>>(cfi, child_cat, child_num,
                                          idx, root_cat, root_num, emb_root, out);
}

// round 13
// speedup vs baseline: 1.3374x; 1.0549x over previous
#include <cuda_runtime.h>
#include <cuda_bf16.h>
#include <cstdint>

#define B_ROOT   8192
#define KFAN     16
#define NCHILD   (B_ROOT * KFAN)     // 131072
#define VOCAB    50000
#define DIM      64
#define CR       8
#define NR       64
#define CC       16
#define NC       128
#define OUTD     32
#define KDIM     (CC * DIM + NC)     // 1152
#define OUTCOLS  (CR * DIM + NR + OUTD)  // 608
#define EPSBN    1e-5f

#define SC_BLKS   (NCHILD / 256)                    // 512
#define SR_BLKS   (B_ROOT / 128)                    // 64
#define PTILES    ((VOCAB + 127) / 128)             // 391
#define PROJ_BLKS (CC * PTILES)                     // 6256
#define BIG1_BLKS (SC_BLKS + SR_BLKS + PROJ_BLKS)   // 6832

#define CH_BLKS   (B_ROOT / 8)                      // 1024 (8 roots / 256-thr block)
#define RT_BLKS   (B_ROOT / 8)                      // 1024
#define BIG2_BLKS (CH_BLKS + RT_BLKS)               // 2048

// big1 proj smem: Ws[64][40] + 8 warps * As[16][68]
#define WS_FLOATS   (DIM * 40)                      // 2560
#define AS_FLOATS   (16 * 68)                       // 1088
#define BIG1_SMEM   ((WS_FLOATS + 8 * AS_FLOATS) * 4)   // 45056 B

// big2 smem: Wn_s[128][40] + 8 warps * { hs[16][68] (aliased buf[16][36]), cats[256], gs[16], pad }
#define WNS_FLOATS  (NC * 40)                       // 5120
#define W2_FLOATS   (16 * 68 + 256 + 16 + 16)       // 1376
#define BIG2_SMEM   ((WNS_FLOATS + 8 * W2_FLOATS) * 4)  // 64512 B

// ---------------- scratch (device globals; allocation-free) ----------------
__device__ __align__(16) double g_sum_c[NC];
__device__ __align__(16) double g_ss_c [NC];
__device__ __align__(16) double g_sum_r[NR];
__device__ __align__(16) double g_ss_r [NR];
__device__ __align__(16) float g_a_c[NC];
__device__ __align__(16) float g_s_c[NC];
__device__ __align__(16) float g_a_r[NR];
__device__ __align__(16) float g_s_r[NR];
__device__ __align__(16) float g_wt[NC * OUTD];   // tf32-rounded numeric W slice [k][o]
// bf16-packed categorical projection: 16 bf16x2 words per (c,v) row = 64 B
__device__ __align__(256) unsigned g_projp[CC * VOCAB * (OUTD / 2)];   // 51.2 MB

// ---------------- helpers ----------------
__device__ __forceinline__ unsigned long long pack2(float a, float b) {
    unsigned long long r;
    asm("mov.b64 %0, {%1, %2};" : "=l"(r) : "f"(a), "f"(b));
    return r;
}
__device__ __forceinline__ void unpack2(unsigned long long v, float& lo, float& hi) {
    asm("mov.b64 {%0, %1}, %2;" : "=f"(lo), "=f"(hi) : "l"(v));
}
__device__ __forceinline__ void fma2(unsigned long long& d, unsigned long long a, unsigned long long b) {
    asm("fma.rn.f32x2 %0, %1, %2, %0;" : "+l"(d) : "l"(a), "l"(b));
}
__device__ __forceinline__ unsigned tf32r(float x) {
    unsigned u;
    asm("cvt.rna.tf32.f32 %0, %1;" : "=r"(u) : "f"(x));
    return u;
}
__device__ __forceinline__ void mma_tf32(float& d0, float& d1, float& d2, float& d3,
                                         unsigned a0, unsigned a1, unsigned a2, unsigned a3,
                                         unsigned b0, unsigned b1) {
    asm volatile("mma.sync.aligned.m16n8k8.row.col.f32.tf32.tf32.f32 "
        "{%0,%1,%2,%3}, {%4,%5,%6,%7}, {%8,%9}, {%0,%1,%2,%3};"
        : "+f"(d0), "+f"(d1), "+f"(d2), "+f"(d3)
        : "r"(a0), "r"(a1), "r"(a2), "r"(a3), "r"(b0), "r"(b1));
}
// accumulate a uint4 of bf16x2 (8 outputs) into 8 fp32 accs
__device__ __forceinline__ void acc8(float* s, uint4 u) {
    unsigned w[4] = {u.x, u.y, u.z, u.w};
#pragma unroll
    for (int j = 0; j < 4; ++j) {
        __nv_bfloat162 b2 = *reinterpret_cast<__nv_bfloat162*>(&w[j]);
        float2 f = __bfloat1622float2(b2);
        s[2 * j]     += f.x;
        s[2 * j + 1] += f.y;
    }
}

// ---------------- kernel 0: reset ----------------
__global__ void k_reset() {
    int t = threadIdx.x;
    if (t < NC) { g_sum_c[t] = 0.0; g_ss_c[t] = 0.0; }
    if (t < NR) { g_sum_r[t] = 0.0; g_ss_r[t] = 0.0; }
}

// ---------------- kernel 1: big1 = stats_child ∪ stats_root ∪ proj(mma) (R12-proven) ----
__global__ __launch_bounds__(256)
void k_big1(const int* __restrict__ cfi, const float* __restrict__ child_num,
            const int* __restrict__ idx, const float* __restrict__ root_num,
            const float* __restrict__ emb_child, const float* __restrict__ W) {
    extern __shared__ float sm[];
    int bid = blockIdx.x;
    int t = threadIdx.x;
    int lane = t & 31;
    int warp = t >> 5;

    if (bid < SC_BLKS) {
        int* rid = (int*)sm;
        rid[t] = cfi[bid * 256 + t];
        __syncthreads();
        int col = t & 127;
        int r0 = (t >> 7) * 128;
        float s[8], ss[8];
#pragma unroll
        for (int u = 0; u < 8; ++u) { s[u] = 0.f; ss[u] = 0.f; }
        for (int r = r0; r < r0 + 128; r += 8) {
            float x[8];
#pragma unroll
            for (int u = 0; u < 8; ++u) {
                int g = rid[r + u];
                x[u] = __ldg(&child_num[(size_t)g * NC + col]);
            }
#pragma unroll
            for (int u = 0; u < 8; ++u) { s[u] += x[u]; ss[u] += x[u] * x[u]; }
        }
        float st  = (s[0]+s[1])+(s[2]+s[3])+((s[4]+s[5])+(s[6]+s[7]));
        float sst = (ss[0]+ss[1])+(ss[2]+ss[3])+((ss[4]+ss[5])+(ss[6]+ss[7]));
        atomicAdd(&g_sum_c[col], (double)st);
        atomicAdd(&g_ss_c[col],  (double)sst);
        return;
    }
    if (bid < SC_BLKS + SR_BLKS) {
        int b = bid - SC_BLKS;
        int* rid = (int*)sm;
        if (t < 128) rid[t] = idx[b * 128 + t];
        __syncthreads();
        int col = t & 63;
        int r0 = (t >> 6) * 32;
        float s[4], ss[4];
#pragma unroll
        for (int u = 0; u < 4; ++u) { s[u] = 0.f; ss[u] = 0.f; }
        for (int r = r0; r < r0 + 32; r += 4) {
            float x[4];
#pragma unroll
            for (int u = 0; u < 4; ++u) {
                int g = rid[r + u];
                x[u] = __ldg(&root_num[(size_t)g * NR + col]);
            }
#pragma unroll
            for (int u = 0; u < 4; ++u) { s[u] += x[u]; ss[u] += x[u] * x[u]; }
        }
        atomicAdd(&g_sum_r[col], (double)((s[0]+s[1])+(s[2]+s[3])));
        atomicAdd(&g_ss_r[col],  (double)((ss[0]+ss[1])+(ss[2]+ss[3])));
        return;
    }

    int pb = bid - (SC_BLKS + SR_BLKS);
    int c  = pb / PTILES;
    int vbase = (pb % PTILES) * 128;

    float* Ws = sm;                               // [64][40] tf32 bits
    float* As = sm + WS_FLOATS + warp * AS_FLOATS;// [16][68] tf32 bits

    for (int i = t; i < DIM * OUTD; i += 256) {
        int o = i >> 6, d = i & 63;
        Ws[d * 40 + o] = __uint_as_float(tf32r(W[(size_t)o * KDIM + c * DIM + d]));
    }
    __syncthreads();

    int v0w = vbase + warp * 16;
    {
        int rsel = lane >> 4;
        int col  = (lane & 15) * 4;
#pragma unroll
        for (int rr = 0; rr < 8; ++rr) {
            int row = 2 * rr + rsel;
            int v = v0w + row;
            float4 e = make_float4(0.f, 0.f, 0.f, 0.f);
            if (v < VOCAB)
                e = *(const float4*)(emb_child + ((size_t)c * VOCAB + v) * DIM + col);
            float4 a;
            a.x = __uint_as_float(tf32r(e.x));
            a.y = __uint_as_float(tf32r(e.y));
            a.z = __uint_as_float(tf32r(e.z));
            a.w = __uint_as_float(tf32r(e.w));
            *(float4*)(As + row * 68 + col) = a;
        }
    }
    __syncwarp();

    float cfr[4][4];
#pragma unroll
    for (int nt = 0; nt < 4; ++nt)
#pragma unroll
        for (int j = 0; j < 4; ++j) cfr[nt][j] = 0.f;

    int gid = lane >> 2, tig = lane & 3;
#pragma unroll
    for (int kt = 0; kt < 8; ++kt) {
        int k0 = kt * 8;
        unsigned a0 = __float_as_uint(As[gid * 68 + k0 + tig]);
        unsigned a1 = __float_as_uint(As[(gid + 8) * 68 + k0 + tig]);
        unsigned a2 = __float_as_uint(As[gid * 68 + k0 + tig + 4]);
        unsigned a3 = __float_as_uint(As[(gid + 8) * 68 + k0 + tig + 4]);
#pragma unroll
        for (int nt = 0; nt < 4; ++nt) {
            unsigned b0 = __float_as_uint(Ws[(k0 + tig) * 40 + nt * 8 + gid]);
            unsigned b1 = __float_as_uint(Ws[(k0 + tig + 4) * 40 + nt * 8 + gid]);
            mma_tf32(cfr[nt][0], cfr[nt][1], cfr[nt][2], cfr[nt][3],
                     a0, a1, a2, a3, b0, b1);
        }
    }

    int vA = v0w + gid, vB = vA + 8;
#pragma unroll
    for (int nt = 0; nt < 4; ++nt) {
        int word = nt * 4 + tig;
        if (vA < VOCAB) {
            __nv_bfloat162 b2 = __float22bfloat162_rn(make_float2(cfr[nt][0], cfr[nt][1]));
            g_projp[((size_t)c * VOCAB + vA) * 16 + word] = *reinterpret_cast<unsigned*>(&b2);
        }
        if (vB < VOCAB) {
            __nv_bfloat162 b2 = __float22bfloat162_rn(make_float2(cfr[nt][2], cfr[nt][3]));
            g_projp[((size_t)c * VOCAB + vB) * 16 + word] = *reinterpret_cast<unsigned*>(&b2);
        }
    }
}

// ---------------- kernel 2: finalize BN + tf32 numeric W slice ----------------
__global__ __launch_bounds__(1024)
void k_finalize(const float* __restrict__ gamma_c, const float* __restrict__ beta_c,
                const float* __restrict__ gamma_r, const float* __restrict__ beta_r,
                const float* __restrict__ W) {
    int t = threadIdx.x;
    if (t < NC) {
        double m = g_sum_c[t] * (1.0 / (double)NCHILD);
        double v = g_ss_c[t] * (1.0 / (double)NCHILD) - m * m;
        float a = gamma_c[t] * rsqrtf((float)v + EPSBN);
        g_a_c[t] = a;
        g_s_c[t] = beta_c[t] - (float)m * a;
    }
    if (t < NR) {
        double m = g_sum_r[t] * (1.0 / (double)B_ROOT);
        double v = g_ss_r[t] * (1.0 / (double)B_ROOT) - m * m;
        float a = gamma_r[t] * rsqrtf((float)v + EPSBN);
        g_a_r[t] = a;
        g_s_r[t] = beta_r[t] - (float)m * a;
    }
    // g_wt[k][o] = tf32(W[o][CC*DIM + k])   (unfolded; BN applied to h)
    for (int i = t; i < NC * OUTD; i += 1024) {
        int k = i >> 5, o = i & 31;
        g_wt[i] = __uint_as_float(tf32r(W[(size_t)o * KDIM + CC * DIM + k]));
    }
}

// ---------------- kernel 3: big2 = child (coop gather + k-chunked tf32 MMA) ∪ root ----
__global__ __launch_bounds__(256, 3)
void k_big2(const int* __restrict__ cfi, const int* __restrict__ child_cat,
            const float* __restrict__ child_num,
            const int* __restrict__ idx, const int* __restrict__ root_cat,
            const float* __restrict__ root_num, const float* __restrict__ emb_root,
            const float* __restrict__ bias,
            float* __restrict__ out) {
    extern __shared__ float sm[];
    int bid = blockIdx.x;
    int t = threadIdx.x;
    int lane = t & 31;
    int warp = t >> 5;

    if (bid >= CH_BLKS) {
        // ---- root part: one warp per root row ----
        int rr = (bid - CH_BLKS) * 8 + warp;
        int g = idx[rr];
        const int* cr = root_cat + (size_t)g * CR;
        float* orow = out + (size_t)rr * OUTCOLS;
#pragma unroll
        for (int c = 0; c < CR; ++c) {
            int v = cr[c];
            const float2* e = (const float2*)(emb_root + ((size_t)c * VOCAB + v) * DIM);
            *(float2*)(orow + c * DIM + lane * 2) = e[lane];
        }
        float2 x  = *(const float2*)(root_num + (size_t)g * NR + lane * 2);
        float2 a  = ((const float2*)g_a_r)[lane];
        float2 sh = ((const float2*)g_s_r)[lane];
        float2 y;
        y.x = fmaf(x.x, a.x, sh.x);
        y.y = fmaf(x.y, a.y, sh.y);
        *(float2*)(orow + CR * DIM + lane * 2) = y;
        return;
    }

    // ---- child: warp = one root (16 rows) ----
    float* Wn_s = sm;                                   // [128][40] tf32 bits
    float* wb   = sm + WNS_FLOATS + warp * W2_FLOATS;
    float* hs   = wb;                                   // [16][68] tf32 bits (aliased buf[16][36] later)
    float* buf  = hs;
    int*   cats = (int*)(wb + 16 * 68);                 // [16][16]
    int*   gs   = cats + 256;                           // [16]

    for (int i = t; i < NC * OUTD; i += 256) {
        int k = i >> 5, o = i & 31;
        Wn_s[k * 40 + o] = g_wt[i];
    }
    __syncthreads();

    int root = bid * 8 + warp;
    if (lane < 16) gs[lane] = cfi[root * KFAN + lane];
    __syncwarp();
    {
        int e1 = lane, e2 = lane + 32;
        ((int4*)cats)[e1] = ((const int4*)(child_cat + (size_t)gs[e1 >> 2] * CC))[e1 & 3];
        ((int4*)cats)[e2] = ((const int4*)(child_cat + (size_t)gs[e2 >> 2] * CC))[e2 & 3];
    }
    __syncwarp();

    // cooperative cat gather: lane (rA = lane>>2, m = lane&3); rB = rA+8.
    // one instruction touches 8 distinct 64B rows (4 lanes consecutive per row).
    float s[16];
#pragma unroll
    for (int j = 0; j < 16; ++j) s[j] = 0.f;
    int rA = lane >> 2, m = lane & 3, rB = rA + 8;
#pragma unroll
    for (int c = 0; c < CC; ++c) {
        uint4 ua = ((const uint4*)(g_projp + ((size_t)c * VOCAB + cats[rA * 16 + c]) * 16))[m];
        uint4 ub = ((const uint4*)(g_projp + ((size_t)c * VOCAB + cats[rB * 16 + c]) * 16))[m];
        acc8(s, ua);
        acc8(s + 8, ub);
    }

    // numeric GEMM [16x128]@[128x32] via tf32 MMA, k staged in 2 chunks of 64
    float cfr[4][4];
#pragma unroll
    for (int nt = 0; nt < 4; ++nt)
#pragma unroll
        for (int j = 0; j < 4; ++j) cfr[nt][j] = 0.f;

    int gid = lane >> 2, tig = lane & 3;
    int cg  = lane & 15, rof = lane >> 4;
#pragma unroll
    for (int kh = 0; kh < 2; ++kh) {
        __syncwarp();
        float4 a4 = *(const float4*)(g_a_c + kh * 64 + cg * 4);
        float4 s4 = *(const float4*)(g_s_c + kh * 64 + cg * 4);
#pragma unroll
        for (int j = 0; j < 8; ++j) {
            int r = j * 2 + rof;
            float4 x = *(const float4*)(child_num + (size_t)gs[r] * NC + kh * 64 + cg * 4);
            uint4 hv;
            hv.x = tf32r(fmaf(x.x, a4.x, s4.x));
            hv.y = tf32r(fmaf(x.y, a4.y, s4.y));
            hv.z = tf32r(fmaf(x.z, a4.z, s4.z));
            hv.w = tf32r(fmaf(x.w, a4.w, s4.w));
            *(uint4*)(hs + r * 68 + cg * 4) = hv;
        }
        __syncwarp();
#pragma unroll
        for (int kt = 0; kt < 8; ++kt) {
            int k0 = kt * 8;                      // local k within chunk
            unsigned a0 = __float_as_uint(hs[gid * 68 + k0 + tig]);
            unsigned a1 = __float_as_uint(hs[(gid + 8) * 68 + k0 + tig]);
            unsigned a2 = __float_as_uint(hs[gid * 68 + k0 + tig + 4]);
            unsigned a3 = __float_as_uint(hs[(gid + 8) * 68 + k0 + tig + 4]);
            int kg = kh * 64 + k0 + tig;          // global k
#pragma unroll
            for (int nt = 0; nt < 4; ++nt) {
                unsigned b0 = __float_as_uint(Wn_s[kg * 40 + nt * 8 + gid]);
                unsigned b1 = __float_as_uint(Wn_s[(kg + 4) * 40 + nt * 8 + gid]);
                mma_tf32(cfr[nt][0], cfr[nt][1], cfr[nt][2], cfr[nt][3],
                         a0, a1, a2, a3, b0, b1);
            }
        }
    }
    __syncwarp();

    // cat partials -> buf (aliases hs; all MMA reads done)
    *(float4*)(buf + rA * 36 + 8 * m)     = make_float4(s[0], s[1], s[2], s[3]);
    *(float4*)(buf + rA * 36 + 8 * m + 4) = make_float4(s[4], s[5], s[6], s[7]);
    *(float4*)(buf + rB * 36 + 8 * m)     = make_float4(s[8], s[9], s[10], s[11]);
    *(float4*)(buf + rB * 36 + 8 * m + 4) = make_float4(s[12], s[13], s[14], s[15]);
    __syncwarp();

    // add MMA fragments (distinct (r,o) owners)
#pragma unroll
    for (int nt = 0; nt < 4; ++nt) {
        int o0 = nt * 8 + 2 * tig;
        buf[gid * 36 + o0]           += cfr[nt][0];
        buf[gid * 36 + o0 + 1]       += cfr[nt][1];
        buf[(gid + 8) * 36 + o0]     += cfr[nt][2];
        buf[(gid + 8) * 36 + o0 + 1] += cfr[nt][3];
    }
    __syncwarp();

    // epilogue: lane = output column; relu + mean over 16 rows; coalesced store
    {
        float bp = __ldg(&bias[lane]);
        float acc = 0.f;
#pragma unroll
        for (int r = 0; r < 16; ++r)
            acc += fmaxf(buf[r * 36 + lane] + bp, 0.f);
        out[(size_t)root * OUTCOLS + CR * DIM + NR + lane] = acc * (1.0f / (float)KFAN);
    }
}

// ---------------- launch ----------------
extern "C" void kernel_launch(void* const* d_in, const int* in_sizes, int n_in,
                              void* d_out, int out_size) {
    const int *idx = nullptr, *cfi = nullptr, *root_cat = nullptr, *child_cat = nullptr;
    const float *root_num = nullptr, *child_num = nullptr;
    const float *emb_root = nullptr, *emb_child = nullptr;
    const float *W = nullptr, *bias = nullptr;
    const float *gamma_r = nullptr, *beta_r = nullptr, *gamma_c = nullptr, *beta_c = nullptr;

    for (int i = 0; i < n_in; ++i) {
        long long s = in_sizes[i];
        void* p = d_in[i];
        switch (s) {
            case 8192:      idx = (const int*)p; break;
            case 131072:    cfi = (const int*)p; break;
            case 1600000:   root_cat  = (const int*)p; break;
            case 8000000:   child_cat = (const int*)p; break;
            case 12800000:  root_num  = (const float*)p; break;
            case 64000000:  child_num = (const float*)p; break;
            case 25600000:  emb_root  = (const float*)p; break;
            case 51200000:  emb_child = (const float*)p; break;
            case 36864:     W = (const float*)p; break;
            case 32:        bias = (const float*)p; break;
            case 64:
                if (!gamma_r) gamma_r = (const float*)p; else beta_r = (const float*)p;
                break;
            case 128:
                if (!gamma_c) gamma_c = (const float*)p; else beta_c = (const float*)p;
                break;
            default: break;
        }
    }

    float* out = (float*)d_out;

    cudaFuncSetAttribute(k_big1, cudaFuncAttributeMaxDynamicSharedMemorySize, BIG1_SMEM);
    cudaFuncSetAttribute(k_big2, cudaFuncAttributeMaxDynamicSharedMemorySize, BIG2_SMEM);

    k_reset<<<1, 256>>>();
    k_big1<<<BIG1_BLKS, 256, BIG1_SMEM>>>(cfi, child_num, idx, root_num, emb_child, W);
    k_finalize<<<1, 1024>>>(gamma_c, beta_c, gamma_r, beta_r, W);
    k_big2<<<BIG2_BLKS, 256, BIG2_SMEM>>>(cfi, child_cat, child_num,
                                          idx, root_cat, root_num, emb_root, bias, out);
}